// round 1
// baseline (speedup 1.0000x reference)
#include <cuda_runtime.h>
#include <cstdint>

// PillarScatter: bev[b, c, iy, ix] = emb[b, p, c] for valid pillars, else 0.
// NX = NY = 512 fixed by problem init_kwargs.

#define NXG 512
#define NYG 512

__global__ void pillar_scatter_kernel(const float* __restrict__ emb,
                                      const int*   __restrict__ coords,
                                      const int*   __restrict__ mask,
                                      float*       __restrict__ out,
                                      int BP, int P, int C)
{
    // one thread per (pillar, channel); C=64 channels contiguous per pillar
    long long tid = (long long)blockIdx.x * blockDim.x + threadIdx.x;
    long long total = (long long)BP * C;
    if (tid >= total) return;

    int bp = (int)(tid >> 6);      // C == 64
    int c  = (int)(tid & 63);

    if (mask[bp] <= 0) return;

    int ix = coords[2 * bp + 0];
    int iy = coords[2 * bp + 1];

    int b = bp / P;

    float v = emb[(long long)bp * C + c];

    // out layout: [B, C, NY, NX]
    long long o = (((long long)b * C + c) * NYG + iy) * NXG + ix;
    out[o] = v;
}

extern "C" void kernel_launch(void* const* d_in, const int* in_sizes, int n_in,
                              void* d_out, int out_size)
{
    const float* emb    = (const float*)d_in[0];   // [B, P, C] f32
    const int*   coords = (const int*)  d_in[1];   // [B, P, 2] i32
    const int*   mask   = (const int*)  d_in[2];   // [B, P]    i32

    int BP = in_sizes[2];                 // B*P
    int C  = in_sizes[0] / BP;            // 64
    int B  = out_size / (C * NXG * NYG);  // 4
    int P  = BP / B;

    float* out = (float*)d_out;

    // 1) zero the full BEV grid (harness poisons d_out). HW memset path = full BW.
    cudaMemsetAsync(out, 0, (size_t)out_size * sizeof(float), 0);

    // 2) scatter valid pillars. 64 threads/pillar -> coalesced embedding reads.
    long long total = (long long)BP * C;
    int threads = 256;
    int blocks = (int)((total + threads - 1) / threads);
    pillar_scatter_kernel<<<blocks, threads>>>(emb, coords, mask, out, BP, P, C);
}

// round 2
// speedup vs baseline: 1.5624x; 1.5624x over previous
#include <cuda_runtime.h>
#include <cstdint>

#define NXG   512
#define NYG   512
#define NCELL (NXG * NYG)   // 262144
#define MAXB  8             // scratch sized for up to 8 batches

// scratch: inverse map cell -> global pillar index (bp), -1 = empty
__device__ int g_inv[MAXB * NCELL];

// ---------------------------------------------------------------------------
// Kernel A: init inv map to -1 (vectorized int4)
__global__ void init_inv_kernel(int n_int4)
{
    int i = blockIdx.x * blockDim.x + threadIdx.x;
    if (i < n_int4) {
        ((int4*)g_inv)[i] = make_int4(-1, -1, -1, -1);
    }
}

// ---------------------------------------------------------------------------
// Kernel B: scatter valid pillar indices into inv map
__global__ void build_inv_kernel(const int* __restrict__ coords,
                                 const int* __restrict__ mask,
                                 int BP, int P)
{
    int bp = blockIdx.x * blockDim.x + threadIdx.x;
    if (bp >= BP) return;
    if (mask[bp] <= 0) return;
    int ix = coords[2 * bp + 0];
    int iy = coords[2 * bp + 1];
    int b  = bp / P;
    g_inv[b * NCELL + iy * NXG + ix] = bp;
}

// ---------------------------------------------------------------------------
// Kernel C: write full BEV output as coalesced float4 streams.
// Block = 256 threads, handles 1024 consecutive cells of batch blockIdx.y,
// loops over all C channels. inv read once per quad; emb gathers hit L2.
__global__ void __launch_bounds__(256)
bev_write_kernel(const float* __restrict__ emb,
                 float*       __restrict__ out,
                 int C)
{
    int b        = blockIdx.y;
    int cellBase = (blockIdx.x * 256 + threadIdx.x) * 4;   // 4 cells per thread

    const int4 pi = *(const int4*)(&g_inv[b * NCELL + cellBase]);

    float* obase = out + ((long long)b * C) * NCELL + cellBase;

    const float* e0 = (pi.x >= 0) ? emb + (long long)pi.x * C : nullptr;
    const float* e1 = (pi.y >= 0) ? emb + (long long)pi.y * C : nullptr;
    const float* e2 = (pi.z >= 0) ? emb + (long long)pi.z * C : nullptr;
    const float* e3 = (pi.w >= 0) ? emb + (long long)pi.w * C : nullptr;

    #pragma unroll 8
    for (int c = 0; c < C; c++) {
        float4 v;
        v.x = e0 ? e0[c] : 0.0f;
        v.y = e1 ? e1[c] : 0.0f;
        v.z = e2 ? e2[c] : 0.0f;
        v.w = e3 ? e3[c] : 0.0f;
        *(float4*)(obase + (long long)c * NCELL) = v;
    }
}

// ---------------------------------------------------------------------------
extern "C" void kernel_launch(void* const* d_in, const int* in_sizes, int n_in,
                              void* d_out, int out_size)
{
    const float* emb    = (const float*)d_in[0];   // [B, P, C] f32
    const int*   coords = (const int*)  d_in[1];   // [B, P, 2] i32
    const int*   mask   = (const int*)  d_in[2];   // [B, P]    i32

    int BP = in_sizes[2];                 // B*P
    int C  = in_sizes[0] / BP;            // 64
    int B  = out_size / (C * NCELL);      // 4
    int P  = BP / B;

    float* out = (float*)d_out;

    // A) inv = -1
    {
        int n_int4 = (B * NCELL) / 4;
        int threads = 256;
        init_inv_kernel<<<(n_int4 + threads - 1) / threads, threads>>>(n_int4);
    }
    // B) scatter pillar indices
    {
        int threads = 256;
        build_inv_kernel<<<(BP + threads - 1) / threads, threads>>>(coords, mask, BP, P);
    }
    // C) full coalesced output write
    {
        dim3 grid(NCELL / 1024, B);   // 256 x B blocks
        bev_write_kernel<<<grid, 256>>>(emb, out, C);
    }
}